// round 8
// baseline (speedup 1.0000x reference)
#include <cuda_runtime.h>
#include <cstdint>

#define NN 100000
#define FF 32
#define DD 3
#define OO 32

__device__ float g_accum[NN * FF];

// ---------------------------------------------------------------------------
// Edge kernel v4 (self-prepping): 8 edges per warp-iteration.
//   lane = 8*g + q : g = edge slot (0..3), q = feature quad (0..7)
// Cooperative loads: ONE LDG for 16 indices (lanes 0-15), ONE LDG for 24
// pseudo floats (lanes 0-23); SHFL distribution; two independent
// gather -> red.global.add.v4.f32 chains.
// Gaussian params loaded per-lane directly from mu/sigma (one-time).
// Edge dtype probed in-warp via ballot (int64 => odd 32-bit words all zero).
// ---------------------------------------------------------------------------
__global__ void __launch_bounds__(256) edge_kernel(
    const float* __restrict__ x,
    const int* __restrict__ ei32,
    const float* __restrict__ pseudo,
    const float* __restrict__ mu,
    const float* __restrict__ sigma,
    int E) {
    const int lane  = threadIdx.x & 31;
    const int g     = lane >> 3;
    const int fbase = (lane & 7) * 4;
    const int warp  = (blockIdx.x * blockDim.x + threadIdx.x) >> 5;
    const int nwarps = (gridDim.x * blockDim.x) >> 5;
    const unsigned FULL = 0xffffffffu;
    const long long* __restrict__ ei64 = (const long long*)ei32;

    // dtype probe: odd 32-bit words of first 32 entries; all zero => int64
    {
        int hv = ei32[2 * lane + 1];
        unsigned nz = __ballot_sync(FULL, hv != 0);
        // fallthrough: is64 computed below
        __shared__ int dummy;  (void)dummy;
        // store in register:
        // (ballot identical across warp; no divergence)
        // is64 flag:
        // nz == 0 -> int64
        // use it directly below
        // (kept in a const for clarity)
        const int is64_ = (nz == 0);
        // gaussian params per lane (one-time broadcast-ish loads, L2-hot)
        float mu0[4], mu1[4], mu2[4], c0[4], c1[4], c2[4];
#pragma unroll
        for (int j = 0; j < 4; j++) {
            int f = fbase + j;
            mu0[j] = mu[f * DD + 0];
            mu1[j] = mu[f * DD + 1];
            mu2[j] = mu[f * DD + 2];
            float s0 = sigma[f * DD + 0];
            float s1 = sigma[f * DD + 1];
            float s2 = sigma[f * DD + 2];
            const float k = -0.5f * 1.4426950408889634f;
            c0[j] = k / (1e-14f + s0 * s0);
            c1[j] = k / (1e-14f + s1 * s1);
            c2[j] = k / (1e-14f + s2 * s2);
        }

        for (long long eb = (long long)warp * 8; eb < E; eb += (long long)nwarps * 8) {
            int idx = 0;
            {
                long long epos = eb + (lane & 7);
                if (lane < 16 && epos < E) {
                    long long a = (lane < 8) ? epos : epos + (long long)E;
                    idx = is64_ ? (int)ei64[a] : ei32[a];
                }
            }
            float pv = 0.f;
            {
                long long ppos = eb * 3 + lane;
                if (lane < 24 && ppos < (long long)E * 3) pv = pseudo[ppos];
            }

            const int rA = __shfl_sync(FULL, idx, g);
            const int rB = __shfl_sync(FULL, idx, 4 + g);
            const int cA = __shfl_sync(FULL, idx, 8 + g);
            const int cB = __shfl_sync(FULL, idx, 12 + g);
            const float p0A = __shfl_sync(FULL, pv, 3 * g + 0);
            const float p1A = __shfl_sync(FULL, pv, 3 * g + 1);
            const float p2A = __shfl_sync(FULL, pv, 3 * g + 2);
            const float p0B = __shfl_sync(FULL, pv, 12 + 3 * g + 0);
            const float p1B = __shfl_sync(FULL, pv, 12 + 3 * g + 1);
            const float p2B = __shfl_sync(FULL, pv, 12 + 3 * g + 2);

            const bool aval = (eb + g) < E;
            const bool bval = (eb + 4 + g) < E;

            float4 xa = make_float4(0.f, 0.f, 0.f, 0.f);
            float4 xb = make_float4(0.f, 0.f, 0.f, 0.f);
            if (aval) xa = *reinterpret_cast<const float4*>(x + (size_t)cA * FF + fbase);
            if (bval) xb = *reinterpret_cast<const float4*>(x + (size_t)cB * FF + fbase);

            float xaj[4] = {xa.x, xa.y, xa.z, xa.w};
            float xbj[4] = {xb.x, xb.y, xb.z, xb.w};
            float vA[4], vB[4];
#pragma unroll
            for (int j = 0; j < 4; j++) {
                float d0 = p0A - mu0[j], d1 = p1A - mu1[j], d2 = p2A - mu2[j];
                float lw = d0 * d0 * c0[j] + d1 * d1 * c1[j] + d2 * d2 * c2[j];
                vA[j] = exp2f(lw) * xaj[j];
            }
#pragma unroll
            for (int j = 0; j < 4; j++) {
                float d0 = p0B - mu0[j], d1 = p1B - mu1[j], d2 = p2B - mu2[j];
                float lw = d0 * d0 * c0[j] + d1 * d1 * c1[j] + d2 * d2 * c2[j];
                vB[j] = exp2f(lw) * xbj[j];
            }

            if (aval) {
                float* dst = g_accum + (size_t)rA * FF + fbase;
                asm volatile("red.global.add.v4.f32 [%0], {%1, %2, %3, %4};"
                             :: "l"(dst), "f"(vA[0]), "f"(vA[1]), "f"(vA[2]), "f"(vA[3])
                             : "memory");
            }
            if (bval) {
                float* dst = g_accum + (size_t)rB * FF + fbase;
                asm volatile("red.global.add.v4.f32 [%0], {%1, %2, %3, %4};"
                             :: "l"(dst), "f"(vB[0]), "f"(vB[1]), "f"(vB[2]), "f"(vB[3])
                             : "memory");
            }
        }
    }
}

// ---------------------------------------------------------------------------
// Linear epilogue (R7 winner, unchanged): smem-tile broadcast, W registers.
// ---------------------------------------------------------------------------
__global__ void __launch_bounds__(256) linear_kernel(
    const float* __restrict__ W,
    const float* __restrict__ b,
    float* __restrict__ out,
    int N) {
    __shared__ float Ws[FF][FF + 1];
    __shared__ float bs[OO];
    __shared__ float As[8][32][36];

    const int tid = threadIdx.x;
    for (int i = tid; i < FF * OO; i += 256)
        Ws[i >> 5][i & 31] = W[i];
    if (tid < OO) bs[tid] = b[tid];
    __syncthreads();

    const int lane = tid & 31;
    const int w    = tid >> 5;

    float wreg[FF];
#pragma unroll
    for (int f = 0; f < FF; f++) wreg[f] = Ws[lane][f];
    const float bias = bs[lane];

    const int node0 = (blockIdx.x * 8 + w) * 32;
    if (node0 >= N) return;

#pragma unroll
    for (int r = 0; r < 8; r++) {
        int idx = r * 32 + lane;
        int n   = idx >> 3;
        int f4  = idx & 7;
        float4 v = make_float4(0.f, 0.f, 0.f, 0.f);
        if (node0 + n < N)
            v = *reinterpret_cast<const float4*>(g_accum + (size_t)(node0 + n) * FF + f4 * 4);
        *reinterpret_cast<float4*>(&As[w][n][f4 * 4]) = v;
    }
    __syncwarp();

    const int nmax = min(32, N - node0);
#pragma unroll 4
    for (int n = 0; n < 32; n++) {
        if (n >= nmax) break;
        float s0 = bias, s1 = 0.f, s2 = 0.f, s3 = 0.f;
#pragma unroll
        for (int f4 = 0; f4 < 8; f4++) {
            float4 a = *reinterpret_cast<const float4*>(&As[w][n][f4 * 4]);
            s0 += a.x * wreg[f4 * 4 + 0];
            s1 += a.y * wreg[f4 * 4 + 1];
            s2 += a.z * wreg[f4 * 4 + 2];
            s3 += a.w * wreg[f4 * 4 + 3];
        }
        out[(size_t)(node0 + n) * OO + lane] = (s0 + s1) + (s2 + s3);
    }
}

// ---------------------------------------------------------------------------
extern "C" void kernel_launch(void* const* d_in, const int* in_sizes, int n_in,
                              void* d_out, int out_size) {
    const float* x   = (const float*)d_in[0];
    const int*   ei  = (const int*)d_in[1];
    const float* ps  = (const float*)d_in[2];
    const float* mu  = (const float*)d_in[3];
    const float* sg  = (const float*)d_in[4];
    const float* W   = (const float*)d_in[5];
    const float* b   = (const float*)d_in[6];
    float*       out = (float*)d_out;

    const int E = in_sizes[1] / 2;
    const int N = in_sizes[0] / FF;

    void* accum_ptr = nullptr;
    cudaGetSymbolAddress(&accum_ptr, g_accum);
    cudaMemsetAsync(accum_ptr, 0, (size_t)NN * FF * sizeof(float), 0);

    edge_kernel<<<148 * 8, 256>>>(x, ei, ps, mu, sg, E);
    linear_kernel<<<(N + 255) / 256, 256>>>(W, b, out, N);
}